// round 1
// baseline (speedup 1.0000x reference)
#include <cuda_runtime.h>
#include <math.h>

#define BB 16
#define NN 2048
#define DD 768

// ---- scratch (no dynamic allocation allowed) ----
__device__ float g_fn[(size_t)BB * NN * DD];            // normalized features, 96 MB
__device__ float g_sim[(size_t)BB * NN * NN];           // similarity, 256 MB
__device__ float g_rowsum[BB * NN];
__device__ int   g_order[BB * NN];

__device__ __forceinline__ void argmax_combine(float& v, int& i, float v2, int i2) {
    if (v2 > v || (v2 == v && i2 < i)) { v = v2; i = i2; }
}

// ---------------- K1: normalize feature rows ----------------
__global__ void knorm(const float* __restrict__ f) {
    const int row = blockIdx.x;                       // b*NN + n
    const float* src = f + (size_t)row * DD;
    float s = 0.f;
    for (int i = threadIdx.x; i < DD; i += 256) { float v = src[i]; s += v * v; }
    for (int o = 16; o; o >>= 1) s += __shfl_down_sync(0xffffffffu, s, o);
    __shared__ float red[8];
    const int w = threadIdx.x >> 5, l = threadIdx.x & 31;
    if (l == 0) red[w] = s;
    __syncthreads();
    if (w == 0) {
        s = (l < 8) ? red[l] : 0.f;
        for (int o = 4; o; o >>= 1) s += __shfl_down_sync(0xffffffffu, s, o);
        if (l == 0) red[0] = 1.0f / fmaxf(sqrtf(s), 1e-12f);
    }
    __syncthreads();
    const float scale = red[0];
    float* dst = g_fn + (size_t)row * DD;
    for (int i = threadIdx.x; i < DD; i += 256) dst[i] = src[i] * scale;
}

// ---------------- K2: SGEMM (fn @ fn^T) + spatial epilogue ----------------
// 128x128 tile per CTA, BK=16, 256 threads, 8x8 microtile.
__global__ void __launch_bounds__(256) kgemm(const float* __restrict__ coords) {
    __shared__ float As[16][128];
    __shared__ float Bs[16][128];
    __shared__ float2 rc[128];
    __shared__ float2 cc[128];

    const int b  = blockIdx.z;
    const int tm = blockIdx.y * 128;
    const int tn = blockIdx.x * 128;
    const float*  F = g_fn + (size_t)b * NN * DD;
    const float2* C = (const float2*)(coords + (size_t)b * NN * 2);
    const int tid = threadIdx.x;

    if (tid < 128) rc[tid] = C[tm + tid];
    else           cc[tid - 128] = C[tn + tid - 128];

    const int lr = tid >> 2;            // 0..63
    const int lc = (tid & 3) << 2;      // 0,4,8,12
    const int ty = tid >> 4;            // 0..15
    const int tx = tid & 15;            // 0..15

    float acc[8][8];
#pragma unroll
    for (int i = 0; i < 8; i++)
#pragma unroll
        for (int j = 0; j < 8; j++) acc[i][j] = 0.f;

    for (int k0 = 0; k0 < DD; k0 += 16) {
#pragma unroll
        for (int r = 0; r < 2; r++) {
            const int row = lr + r * 64;
            const float4 a  = *(const float4*)(F + (size_t)(tm + row) * DD + k0 + lc);
            As[lc + 0][row] = a.x; As[lc + 1][row] = a.y;
            As[lc + 2][row] = a.z; As[lc + 3][row] = a.w;
            const float4 bb = *(const float4*)(F + (size_t)(tn + row) * DD + k0 + lc);
            Bs[lc + 0][row] = bb.x; Bs[lc + 1][row] = bb.y;
            Bs[lc + 2][row] = bb.z; Bs[lc + 3][row] = bb.w;
        }
        __syncthreads();
#pragma unroll
        for (int k = 0; k < 16; k++) {
            float ra[8], rb[8];
#pragma unroll
            for (int i = 0; i < 8; i++) ra[i] = As[k][ty * 8 + i];
#pragma unroll
            for (int j = 0; j < 8; j++) rb[j] = Bs[k][tx * 8 + j];
#pragma unroll
            for (int i = 0; i < 8; i++)
#pragma unroll
                for (int j = 0; j < 8; j++) acc[i][j] = fmaf(ra[i], rb[j], acc[i][j]);
        }
        __syncthreads();
    }

    float* S = g_sim + (size_t)b * NN * NN;
#pragma unroll
    for (int i = 0; i < 8; i++) {
        const int gi = tm + ty * 8 + i;
        const float2 r2 = rc[ty * 8 + i];
        float out[8];
#pragma unroll
        for (int j = 0; j < 8; j++) {
            const float2 c2 = cc[tx * 8 + j];
            const float dx = r2.x - c2.x, dy = r2.y - c2.y;
            const float sp = expf(-(dx * dx + dy * dy) * (1.0f / 10000.0f));
            out[j] = acc[i][j] + 0.5f * sp;
        }
        float4* op = (float4*)(S + (size_t)gi * NN + tn + tx * 8);
        op[0] = make_float4(out[0], out[1], out[2], out[3]);
        op[1] = make_float4(out[4], out[5], out[6], out[7]);
    }
}

// ---------------- K3: deterministic row sums ----------------
__global__ void krowsum() {
    const int row = blockIdx.x;                       // b*NN + i
    const float* S = g_sim + (size_t)row * NN;
    float s = 0.f;
    for (int j = threadIdx.x; j < NN; j += 256) s += S[j];
    for (int o = 16; o; o >>= 1) s += __shfl_down_sync(0xffffffffu, s, o);
    __shared__ float red[8];
    const int w = threadIdx.x >> 5, l = threadIdx.x & 31;
    if (l == 0) red[w] = s;
    __syncthreads();
    if (w == 0) {
        s = (l < 8) ? red[l] : 0.f;
        for (int o = 4; o; o >>= 1) s += __shfl_down_sync(0xffffffffu, s, o);
        if (l == 0) g_rowsum[row] = s;
    }
}

// ---------------- K4: greedy traversal, 1 CTA per batch ----------------
__global__ void __launch_bounds__(1024) kgreedy() {
    const int b = blockIdx.x;
    __shared__ unsigned vis[NN / 32];
    __shared__ float sval[32];
    __shared__ int   sidx[32];
    __shared__ int   s_cur;
    const int tid = threadIdx.x;
    const int w = tid >> 5, l = tid & 31;

    if (tid < NN / 32) vis[tid] = 0u;
    __syncthreads();

    // start node: argmax of row sums (tie -> smallest index, matching jnp.argmax)
    {
        const float* rs = g_rowsum + b * NN;
        float v = rs[tid]; int bi = tid;
        argmax_combine(v, bi, rs[tid + 1024], tid + 1024);
        for (int o = 16; o; o >>= 1) {
            const float ov = __shfl_down_sync(0xffffffffu, v, o);
            const int   oi = __shfl_down_sync(0xffffffffu, bi, o);
            argmax_combine(v, bi, ov, oi);
        }
        if (l == 0) { sval[w] = v; sidx[w] = bi; }
        __syncthreads();
        if (tid < 32) {
            v = sval[tid]; bi = sidx[tid];
            for (int o = 16; o; o >>= 1) {
                const float ov = __shfl_down_sync(0xffffffffu, v, o);
                const int   oi = __shfl_down_sync(0xffffffffu, bi, o);
                argmax_combine(v, bi, ov, oi);
            }
            if (tid == 0) {
                s_cur = bi;
                vis[bi >> 5] |= (1u << (bi & 31));
                g_order[b * NN] = bi;
            }
        }
    }

    for (int step = 1; step < NN; step++) {
        __syncthreads();                      // publish s_cur / vis
        const int cur = s_cur;
        const float* row = g_sim + ((size_t)b * NN + cur) * NN;

        const int j0 = tid;
        float x0 = row[j0];
        if ((vis[j0 >> 5] >> (j0 & 31)) & 1u) x0 = -3.0e38f;
        float v = x0; int bi = j0;

        const int j1 = tid + 1024;
        float x1 = row[j1];
        if ((vis[j1 >> 5] >> (j1 & 31)) & 1u) x1 = -3.0e38f;
        argmax_combine(v, bi, x1, j1);

        for (int o = 16; o; o >>= 1) {
            const float ov = __shfl_down_sync(0xffffffffu, v, o);
            const int   oi = __shfl_down_sync(0xffffffffu, bi, o);
            argmax_combine(v, bi, ov, oi);
        }
        if (l == 0) { sval[w] = v; sidx[w] = bi; }
        __syncthreads();
        if (tid < 32) {
            v = sval[tid]; bi = sidx[tid];
            for (int o = 16; o; o >>= 1) {
                const float ov = __shfl_down_sync(0xffffffffu, v, o);
                const int   oi = __shfl_down_sync(0xffffffffu, bi, o);
                argmax_combine(v, bi, ov, oi);
            }
            if (tid == 0) {
                s_cur = bi;
                vis[bi >> 5] |= (1u << (bi & 31));
                g_order[b * NN + step] = bi;
            }
        }
    }
}

// ---------------- K5: gather reordered features ----------------
__global__ void kreorder(const float* __restrict__ f, float* __restrict__ out) {
    const int b = blockIdx.y, i = blockIdx.x;
    const int src = g_order[b * NN + i];
    const float4* s = (const float4*)(f + ((size_t)b * NN + src) * DD);
    float4* d = (float4*)(out + ((size_t)b * NN + i) * DD);
    d[threadIdx.x] = s[threadIdx.x];      // 192 threads * 16B = 3072B = DD floats
}

__global__ void korder(float* __restrict__ out) {
    const int t = blockIdx.x * blockDim.x + threadIdx.x;
    if (t < BB * NN) out[(size_t)BB * NN * DD + t] = (float)g_order[t];
}

extern "C" void kernel_launch(void* const* d_in, const int* in_sizes, int n_in,
                              void* d_out, int out_size) {
    const float* features = (const float*)d_in[0];
    const float* coords   = (const float*)d_in[1];
    float* out = (float*)d_out;

    knorm<<<BB * NN, 256>>>(features);

    dim3 gg(NN / 128, NN / 128, BB);
    kgemm<<<gg, 256>>>(coords);

    krowsum<<<BB * NN, 256>>>();

    kgreedy<<<BB, 1024>>>();

    dim3 rg(NN, BB);
    kreorder<<<rg, 192>>>(features, out);

    if ((long long)out_size >= (long long)BB * NN * DD + BB * NN) {
        korder<<<(BB * NN + 255) / 256, 256>>>(out);
    }
}

// round 2
// speedup vs baseline: 1.2306x; 1.2306x over previous
#include <cuda_runtime.h>
#include <math.h>

#define BB 16
#define NN 2048
#define DD 768
#define NT (NN / 128)          // 16 tiles per dim
#define NPAIR (NT * (NT + 1) / 2)   // 136 upper-tri tile pairs

// ---- scratch (no dynamic allocation allowed) ----
__device__ float g_fn[(size_t)BB * NN * DD];            // normalized features, 96 MB
__device__ float g_sim[(size_t)BB * NN * NN];           // similarity, 256 MB
__device__ float g_rowsum[BB * NN];
__device__ int   g_order[BB * NN];

__device__ __forceinline__ void argmax_combine(float& v, int& i, float v2, int i2) {
    if (v2 > v || (v2 == v && i2 < i)) { v = v2; i = i2; }
}

// ---------------- K1: normalize feature rows ----------------
__global__ void knorm(const float* __restrict__ f) {
    const int row = blockIdx.x;                       // b*NN + n
    const float* src = f + (size_t)row * DD;
    float s = 0.f;
    for (int i = threadIdx.x; i < DD; i += 256) { float v = src[i]; s += v * v; }
    for (int o = 16; o; o >>= 1) s += __shfl_down_sync(0xffffffffu, s, o);
    __shared__ float red[8];
    const int w = threadIdx.x >> 5, l = threadIdx.x & 31;
    if (l == 0) red[w] = s;
    __syncthreads();
    if (w == 0) {
        s = (l < 8) ? red[l] : 0.f;
        for (int o = 4; o; o >>= 1) s += __shfl_down_sync(0xffffffffu, s, o);
        if (l == 0) red[0] = 1.0f / fmaxf(sqrtf(s), 1e-12f);
    }
    __syncthreads();
    const float scale = red[0];
    float* dst = g_fn + (size_t)row * DD;
    for (int i = threadIdx.x; i < DD; i += 256) dst[i] = src[i] * scale;
}

// ---------------- K2: SGEMM (fn @ fn^T) + spatial epilogue, symmetric ----------------
// Only upper-triangular 128x128 tiles computed; off-diag tiles mirrored via
// an SMEM transpose so both halves are written coalesced.
__global__ void __launch_bounds__(256) kgemm(const float* __restrict__ coords) {
    __shared__ float As[16][128];
    __shared__ float Bs[16][128];
    __shared__ float2 rc[128];
    __shared__ float2 cc[128];
    __shared__ float tbuf[32][132];

    // decode triangular pair index -> (tmi, tni) with tmi <= tni
    int p = blockIdx.x;
    int tmi = 0;
    while (p >= NT - tmi) { p -= NT - tmi; tmi++; }
    const int tni = tmi + p;

    const int b  = blockIdx.z;
    const int tm = tmi * 128;
    const int tn = tni * 128;
    const float*  F = g_fn + (size_t)b * NN * DD;
    const float2* C = (const float2*)(coords + (size_t)b * NN * 2);
    const int tid = threadIdx.x;

    if (tid < 128) rc[tid] = C[tm + tid];
    else           cc[tid - 128] = C[tn + tid - 128];

    const int lr = tid >> 2;            // 0..63
    const int lc = (tid & 3) << 2;      // 0,4,8,12
    const int ty = tid >> 4;            // 0..15
    const int tx = tid & 15;            // 0..15

    float acc[8][8];
#pragma unroll
    for (int i = 0; i < 8; i++)
#pragma unroll
        for (int j = 0; j < 8; j++) acc[i][j] = 0.f;

    for (int k0 = 0; k0 < DD; k0 += 16) {
#pragma unroll
        for (int r = 0; r < 2; r++) {
            const int row = lr + r * 64;
            const float4 a  = *(const float4*)(F + (size_t)(tm + row) * DD + k0 + lc);
            As[lc + 0][row] = a.x; As[lc + 1][row] = a.y;
            As[lc + 2][row] = a.z; As[lc + 3][row] = a.w;
            const float4 bb = *(const float4*)(F + (size_t)(tn + row) * DD + k0 + lc);
            Bs[lc + 0][row] = bb.x; Bs[lc + 1][row] = bb.y;
            Bs[lc + 2][row] = bb.z; Bs[lc + 3][row] = bb.w;
        }
        __syncthreads();
#pragma unroll
        for (int k = 0; k < 16; k++) {
            float ra[8], rb[8];
#pragma unroll
            for (int i = 0; i < 8; i++) ra[i] = As[k][ty * 8 + i];
#pragma unroll
            for (int j = 0; j < 8; j++) rb[j] = Bs[k][tx * 8 + j];
#pragma unroll
            for (int i = 0; i < 8; i++)
#pragma unroll
                for (int j = 0; j < 8; j++) acc[i][j] = fmaf(ra[i], rb[j], acc[i][j]);
        }
        __syncthreads();
    }

    // epilogue: add spatial term in-place
#pragma unroll
    for (int i = 0; i < 8; i++) {
        const float2 r2 = rc[ty * 8 + i];
#pragma unroll
        for (int j = 0; j < 8; j++) {
            const float2 c2 = cc[tx * 8 + j];
            const float dx = r2.x - c2.x, dy = r2.y - c2.y;
            const float sp = expf(-(dx * dx + dy * dy) * (1.0f / 10000.0f));
            acc[i][j] += 0.5f * sp;
        }
    }

    float* S = g_sim + (size_t)b * NN * NN;
    // normal (upper) tile write
#pragma unroll
    for (int i = 0; i < 8; i++) {
        const int gi = tm + ty * 8 + i;
        float4* op = (float4*)(S + (size_t)gi * NN + tn + tx * 8);
        op[0] = make_float4(acc[i][0], acc[i][1], acc[i][2], acc[i][3]);
        op[1] = make_float4(acc[i][4], acc[i][5], acc[i][6], acc[i][7]);
    }

    // mirror (lower) tile write via smem transpose, coalesced
    if (tmi != tni) {
#pragma unroll
        for (int c0 = 0; c0 < 128; c0 += 32) {
            __syncthreads();
            if (tx >= (c0 >> 3) && tx < (c0 >> 3) + 4) {
#pragma unroll
                for (int j = 0; j < 8; j++)
#pragma unroll
                    for (int i = 0; i < 8; i++)
                        tbuf[tx * 8 + j - c0][ty * 8 + i] = acc[i][j];
            }
            __syncthreads();
            const int cc2 = tid >> 3;             // 0..31 : column (global row gj)
            const int seg = (tid & 7) * 16;       // 16 floats each
            float4* dst = (float4*)(S + (size_t)(tn + c0 + cc2) * NN + tm + seg);
            const float* sr = &tbuf[cc2][seg];
            dst[0] = make_float4(sr[0],  sr[1],  sr[2],  sr[3]);
            dst[1] = make_float4(sr[4],  sr[5],  sr[6],  sr[7]);
            dst[2] = make_float4(sr[8],  sr[9],  sr[10], sr[11]);
            dst[3] = make_float4(sr[12], sr[13], sr[14], sr[15]);
        }
    }
}

// ---------------- K3: deterministic row sums ----------------
__global__ void krowsum() {
    const int row = blockIdx.x;                       // b*NN + i
    const float* S = g_sim + (size_t)row * NN;
    float s = 0.f;
    for (int j = threadIdx.x; j < NN; j += 256) s += S[j];
    for (int o = 16; o; o >>= 1) s += __shfl_down_sync(0xffffffffu, s, o);
    __shared__ float red[8];
    const int w = threadIdx.x >> 5, l = threadIdx.x & 31;
    if (l == 0) red[w] = s;
    __syncthreads();
    if (w == 0) {
        s = (l < 8) ? red[l] : 0.f;
        for (int o = 4; o; o >>= 1) s += __shfl_down_sync(0xffffffffu, s, o);
        if (l == 0) g_rowsum[row] = s;
    }
}

// ---------------- K4: greedy traversal, 1 CTA per batch ----------------
__global__ void __launch_bounds__(1024) kgreedy() {
    const int b = blockIdx.x;
    __shared__ unsigned vis[NN / 32];
    __shared__ float sval[32];
    __shared__ int   sidx[32];
    __shared__ int   s_cur;
    const int tid = threadIdx.x;
    const int w = tid >> 5, l = tid & 31;

    if (tid < NN / 32) vis[tid] = 0u;
    __syncthreads();

    // start node: argmax of row sums (tie -> smallest index, matching jnp.argmax)
    {
        const float* rs = g_rowsum + b * NN;
        float v = rs[tid]; int bi = tid;
        argmax_combine(v, bi, rs[tid + 1024], tid + 1024);
        for (int o = 16; o; o >>= 1) {
            const float ov = __shfl_down_sync(0xffffffffu, v, o);
            const int   oi = __shfl_down_sync(0xffffffffu, bi, o);
            argmax_combine(v, bi, ov, oi);
        }
        if (l == 0) { sval[w] = v; sidx[w] = bi; }
        __syncthreads();
        if (tid < 32) {
            v = sval[tid]; bi = sidx[tid];
            for (int o = 16; o; o >>= 1) {
                const float ov = __shfl_down_sync(0xffffffffu, v, o);
                const int   oi = __shfl_down_sync(0xffffffffu, bi, o);
                argmax_combine(v, bi, ov, oi);
            }
            if (tid == 0) {
                s_cur = bi;
                vis[bi >> 5] |= (1u << (bi & 31));
                g_order[b * NN] = bi;
            }
        }
    }

    for (int step = 1; step < NN; step++) {
        __syncthreads();                      // publish s_cur / vis
        const int cur = s_cur;
        const float* row = g_sim + ((size_t)b * NN + cur) * NN;

        const int j0 = tid;
        float x0 = row[j0];
        if ((vis[j0 >> 5] >> (j0 & 31)) & 1u) x0 = -3.0e38f;
        float v = x0; int bi = j0;

        const int j1 = tid + 1024;
        float x1 = row[j1];
        if ((vis[j1 >> 5] >> (j1 & 31)) & 1u) x1 = -3.0e38f;
        argmax_combine(v, bi, x1, j1);

        for (int o = 16; o; o >>= 1) {
            const float ov = __shfl_down_sync(0xffffffffu, v, o);
            const int   oi = __shfl_down_sync(0xffffffffu, bi, o);
            argmax_combine(v, bi, ov, oi);
        }
        if (l == 0) { sval[w] = v; sidx[w] = bi; }
        __syncthreads();
        if (tid < 32) {
            v = sval[tid]; bi = sidx[tid];
            for (int o = 16; o; o >>= 1) {
                const float ov = __shfl_down_sync(0xffffffffu, v, o);
                const int   oi = __shfl_down_sync(0xffffffffu, bi, o);
                argmax_combine(v, bi, ov, oi);
            }
            if (tid == 0) {
                s_cur = bi;
                vis[bi >> 5] |= (1u << (bi & 31));
                g_order[b * NN + step] = bi;
            }
        }
    }
}

// ---------------- K5: gather reordered features ----------------
__global__ void kreorder(const float* __restrict__ f, float* __restrict__ out) {
    const int b = blockIdx.y, i = blockIdx.x;
    const int src = g_order[b * NN + i];
    const float4* s = (const float4*)(f + ((size_t)b * NN + src) * DD);
    float4* d = (float4*)(out + ((size_t)b * NN + i) * DD);
    d[threadIdx.x] = s[threadIdx.x];      // 192 threads * 16B = 3072B = DD floats
}

__global__ void korder(float* __restrict__ out) {
    const int t = blockIdx.x * blockDim.x + threadIdx.x;
    if (t < BB * NN) out[(size_t)BB * NN * DD + t] = (float)g_order[t];
}

extern "C" void kernel_launch(void* const* d_in, const int* in_sizes, int n_in,
                              void* d_out, int out_size) {
    const float* features = (const float*)d_in[0];
    const float* coords   = (const float*)d_in[1];
    float* out = (float*)d_out;

    knorm<<<BB * NN, 256>>>(features);

    dim3 gg(NPAIR, 1, BB);
    kgemm<<<gg, 256>>>(coords);

    krowsum<<<BB * NN, 256>>>();

    kgreedy<<<BB, 1024>>>();

    dim3 rg(NN, BB);
    kreorder<<<rg, 192>>>(features, out);

    if ((long long)out_size >= (long long)BB * NN * DD + BB * NN) {
        korder<<<(BB * NN + 255) / 256, 256>>>(out);
    }
}

// round 3
// speedup vs baseline: 1.3426x; 1.0910x over previous
#include <cuda_runtime.h>
#include <math.h>

#define BB 16
#define NN 2048
#define DD 768
#define NT (NN / 128)               // 16 tiles per dim
#define NPAIR (NT * (NT + 1) / 2)   // 136 upper-tri tile pairs

typedef unsigned long long ull;

// ---- scratch (no dynamic allocation allowed) ----
__device__ float g_fn[(size_t)BB * NN * DD];    // normalized features, 96 MB
__device__ float g_sim[(size_t)BB * NN * NN];   // similarity, 256 MB
__device__ float g_part[(size_t)BB * NN * NT];  // per-tile row-sum partials, 2 MB
__device__ float g_rowsum[BB * NN];
__device__ int   g_order[BB * NN];

__device__ __forceinline__ void argmax_combine(float& v, int& i, float v2, int i2) {
    if (v2 > v || (v2 == v && i2 < i)) { v = v2; i = i2; }
}

__device__ __forceinline__ ull ffma2(ull a, ull b, ull c) {
    ull d;
    asm("fma.rn.f32x2 %0, %1, %2, %3;" : "=l"(d) : "l"(a), "l"(b), "l"(c));
    return d;
}
__device__ __forceinline__ ull pack2(float x, float y) {
    ull r;
    asm("mov.b64 %0, {%1, %2};" : "=l"(r) : "f"(x), "f"(y));
    return r;
}
__device__ __forceinline__ float2 unpack2(ull a) {
    float2 f;
    asm("mov.b64 {%0, %1}, %2;" : "=f"(f.x), "=f"(f.y) : "l"(a));
    return f;
}

// ---------------- K1: normalize feature rows ----------------
__global__ void knorm(const float* __restrict__ f) {
    const int row = blockIdx.x;                       // b*NN + n
    const float* src = f + (size_t)row * DD;
    float s = 0.f;
    for (int i = threadIdx.x; i < DD; i += 256) { float v = src[i]; s += v * v; }
    for (int o = 16; o; o >>= 1) s += __shfl_down_sync(0xffffffffu, s, o);
    __shared__ float red[8];
    const int w = threadIdx.x >> 5, l = threadIdx.x & 31;
    if (l == 0) red[w] = s;
    __syncthreads();
    if (w == 0) {
        s = (l < 8) ? red[l] : 0.f;
        for (int o = 4; o; o >>= 1) s += __shfl_down_sync(0xffffffffu, s, o);
        if (l == 0) red[0] = 1.0f / fmaxf(sqrtf(s), 1e-12f);
    }
    __syncthreads();
    const float scale = red[0];
    float* dst = g_fn + (size_t)row * DD;
    for (int i = threadIdx.x; i < DD; i += 256) dst[i] = src[i] * scale;
}

// ---------------- K2: symmetric SGEMM + spatial + fused rowsum partials ----------------
struct ShMM { float As[16][128]; float Bs[16][128]; };
union ShU {
    ShMM  mm;
    float tb[32][132];
    float cpart[16][132];
};

__global__ void __launch_bounds__(256, 2) kgemm(const float* __restrict__ coords) {
    __shared__ __align__(16) ShU sh;
    __shared__ float2 rc[128];
    __shared__ float2 cc[128];

    // decode triangular pair index -> (tmi, tni) with tmi <= tni
    int p = blockIdx.x;
    int tmi = 0;
    while (p >= NT - tmi) { p -= NT - tmi; tmi++; }
    const int tni = tmi + p;

    const int b  = blockIdx.z;
    const int tm = tmi * 128;
    const int tn = tni * 128;
    const float*  F = g_fn + (size_t)b * NN * DD;
    const float2* C = (const float2*)(coords + (size_t)b * NN * 2);
    const int tid = threadIdx.x;

    if (tid < 128) rc[tid] = C[tm + tid];
    else           cc[tid - 128] = C[tn + tid - 128];

    const int lr  = tid >> 2;            // 0..63
    const int lc4 = (tid & 3) << 2;      // 0,4,8,12
    const int ty  = tid >> 4;            // 0..15
    const int tx  = tid & 15;            // 0..15

    // initial prefetch of k0 = 0
    float4 pa[2], pb[2];
#pragma unroll
    for (int r = 0; r < 2; r++) {
        const int row = lr + r * 64;
        pa[r] = *(const float4*)(F + (size_t)(tm + row) * DD + lc4);
        pb[r] = *(const float4*)(F + (size_t)(tn + row) * DD + lc4);
    }

    ull acc2[4][8];
#pragma unroll
    for (int i = 0; i < 4; i++)
#pragma unroll
        for (int j = 0; j < 8; j++) acc2[i][j] = 0ull;

    for (int k0 = 0; k0 < DD; k0 += 16) {
        // store prefetched chunk to smem
#pragma unroll
        for (int r = 0; r < 2; r++) {
            const int row = lr + r * 64;
            sh.mm.As[lc4 + 0][row] = pa[r].x; sh.mm.As[lc4 + 1][row] = pa[r].y;
            sh.mm.As[lc4 + 2][row] = pa[r].z; sh.mm.As[lc4 + 3][row] = pa[r].w;
            sh.mm.Bs[lc4 + 0][row] = pb[r].x; sh.mm.Bs[lc4 + 1][row] = pb[r].y;
            sh.mm.Bs[lc4 + 2][row] = pb[r].z; sh.mm.Bs[lc4 + 3][row] = pb[r].w;
        }
        __syncthreads();

        // issue gmem prefetch for next chunk (latency hidden behind FFMA block)
        if (k0 + 16 < DD) {
#pragma unroll
            for (int r = 0; r < 2; r++) {
                const int row = lr + r * 64;
                pa[r] = *(const float4*)(F + (size_t)(tm + row) * DD + k0 + 16 + lc4);
                pb[r] = *(const float4*)(F + (size_t)(tn + row) * DD + k0 + 16 + lc4);
            }
        }

#pragma unroll
        for (int k = 0; k < 16; k++) {
            const ulonglong2 a01 = *(const ulonglong2*)&sh.mm.As[k][ty * 8];
            const ulonglong2 a23 = *(const ulonglong2*)&sh.mm.As[k][ty * 8 + 4];
            const float4 b0 = *(const float4*)&sh.mm.Bs[k][tx * 8];
            const float4 b1 = *(const float4*)&sh.mm.Bs[k][tx * 8 + 4];
            ull av[4] = { a01.x, a01.y, a23.x, a23.y };
            ull bd[8] = { pack2(b0.x, b0.x), pack2(b0.y, b0.y),
                          pack2(b0.z, b0.z), pack2(b0.w, b0.w),
                          pack2(b1.x, b1.x), pack2(b1.y, b1.y),
                          pack2(b1.z, b1.z), pack2(b1.w, b1.w) };
#pragma unroll
            for (int ip = 0; ip < 4; ip++)
#pragma unroll
                for (int j = 0; j < 8; j++)
                    acc2[ip][j] = ffma2(av[ip], bd[j], acc2[ip][j]);
        }
        __syncthreads();
    }

    // unpack accumulators
    float acc[8][8];
#pragma unroll
    for (int ip = 0; ip < 4; ip++)
#pragma unroll
        for (int j = 0; j < 8; j++) {
            const float2 v = unpack2(acc2[ip][j]);
            acc[2 * ip + 0][j] = v.x;
            acc[2 * ip + 1][j] = v.y;
        }

    // spatial epilogue
#pragma unroll
    for (int i = 0; i < 8; i++) {
        const float2 r2 = rc[ty * 8 + i];
#pragma unroll
        for (int j = 0; j < 8; j++) {
            const float2 c2 = cc[tx * 8 + j];
            const float dx = r2.x - c2.x, dy = r2.y - c2.y;
            const float sp = expf(-(dx * dx + dy * dy) * (1.0f / 10000.0f));
            acc[i][j] += 0.5f * sp;
        }
    }

    float* S = g_sim + (size_t)b * NN * NN;
    // upper tile write
#pragma unroll
    for (int i = 0; i < 8; i++) {
        const int gi = tm + ty * 8 + i;
        float4* op = (float4*)(S + (size_t)gi * NN + tn + tx * 8);
        op[0] = make_float4(acc[i][0], acc[i][1], acc[i][2], acc[i][3]);
        op[1] = make_float4(acc[i][4], acc[i][5], acc[i][6], acc[i][7]);
    }

    // fused row-sum partials for rows of this tile (deterministic xor-tree over tx)
#pragma unroll
    for (int i = 0; i < 8; i++) {
        float s = 0.f;
#pragma unroll
        for (int j = 0; j < 8; j++) s += acc[i][j];
#pragma unroll
        for (int o = 8; o; o >>= 1) s += __shfl_xor_sync(0xffffffffu, s, o);
        if (tx == 0)
            g_part[((size_t)b * NN + tm + ty * 8 + i) * NT + tni] = s;
    }

    if (tmi != tni) {
        // column-sum partials -> row sums of the mirrored block
        float cs[8];
#pragma unroll
        for (int j = 0; j < 8; j++) {
            float s = 0.f;
#pragma unroll
            for (int i = 0; i < 8; i++) s += acc[i][j];
            cs[j] = s;
        }
        __syncthreads();
#pragma unroll
        for (int j = 0; j < 8; j++) sh.cpart[ty][tx * 8 + j] = cs[j];
        __syncthreads();
        if (tid < 128) {
            float s = 0.f;
#pragma unroll
            for (int t = 0; t < 16; t++) s += sh.cpart[t][tid];
            g_part[((size_t)b * NN + tn + tid) * NT + tmi] = s;
        }

        // mirror (lower) tile write via smem transpose, coalesced
#pragma unroll
        for (int c0 = 0; c0 < 128; c0 += 32) {
            __syncthreads();
            if (tx >= (c0 >> 3) && tx < (c0 >> 3) + 4) {
#pragma unroll
                for (int j = 0; j < 8; j++)
#pragma unroll
                    for (int i = 0; i < 8; i++)
                        sh.tb[tx * 8 + j - c0][ty * 8 + i] = acc[i][j];
            }
            __syncthreads();
            const int cc2 = tid >> 3;             // 0..31
            const int seg = (tid & 7) * 16;
            float4* dst = (float4*)(S + (size_t)(tn + c0 + cc2) * NN + tm + seg);
            const float* sr = &sh.tb[cc2][seg];
            dst[0] = make_float4(sr[0],  sr[1],  sr[2],  sr[3]);
            dst[1] = make_float4(sr[4],  sr[5],  sr[6],  sr[7]);
            dst[2] = make_float4(sr[8],  sr[9],  sr[10], sr[11]);
            dst[3] = make_float4(sr[12], sr[13], sr[14], sr[15]);
        }
    }
}

// ---------------- K3: reduce per-tile partials to row sums ----------------
__global__ void krowsum() {
    const int row = blockIdx.x * 256 + threadIdx.x;   // BB*NN rows
    if (row >= BB * NN) return;
    const float* pp = g_part + (size_t)row * NT;
    float s = 0.f;
#pragma unroll
    for (int t = 0; t < NT; t++) s += pp[t];
    g_rowsum[row] = s;
}

// ---------------- K4: greedy traversal, 1 CTA per batch ----------------
__global__ void __launch_bounds__(1024) kgreedy() {
    const int b = blockIdx.x;
    __shared__ unsigned vis[NN / 32];
    __shared__ float sval[32];
    __shared__ int   sidx[32];
    __shared__ int   s_cur;
    const int tid = threadIdx.x;
    const int w = tid >> 5, l = tid & 31;

    if (tid < NN / 32) vis[tid] = 0u;
    __syncthreads();

    // start node: argmax of row sums (tie -> smallest index)
    {
        const float* rs = g_rowsum + b * NN;
        float v = rs[tid]; int bi = tid;
        argmax_combine(v, bi, rs[tid + 1024], tid + 1024);
        for (int o = 16; o; o >>= 1) {
            const float ov = __shfl_down_sync(0xffffffffu, v, o);
            const int   oi = __shfl_down_sync(0xffffffffu, bi, o);
            argmax_combine(v, bi, ov, oi);
        }
        if (l == 0) { sval[w] = v; sidx[w] = bi; }
        __syncthreads();
        if (tid < 32) {
            v = sval[tid]; bi = sidx[tid];
            for (int o = 16; o; o >>= 1) {
                const float ov = __shfl_down_sync(0xffffffffu, v, o);
                const int   oi = __shfl_down_sync(0xffffffffu, bi, o);
                argmax_combine(v, bi, ov, oi);
            }
            if (tid == 0) {
                s_cur = bi;
                vis[bi >> 5] |= (1u << (bi & 31));
                g_order[b * NN] = bi;
            }
        }
    }

    for (int step = 1; step < NN; step++) {
        __syncthreads();
        const int cur = s_cur;
        const float* row = g_sim + ((size_t)b * NN + cur) * NN;

        const int j0 = tid;
        float x0 = row[j0];
        if ((vis[j0 >> 5] >> (j0 & 31)) & 1u) x0 = -3.0e38f;
        float v = x0; int bi = j0;

        const int j1 = tid + 1024;
        float x1 = row[j1];
        if ((vis[j1 >> 5] >> (j1 & 31)) & 1u) x1 = -3.0e38f;
        argmax_combine(v, bi, x1, j1);

        for (int o = 16; o; o >>= 1) {
            const float ov = __shfl_down_sync(0xffffffffu, v, o);
            const int   oi = __shfl_down_sync(0xffffffffu, bi, o);
            argmax_combine(v, bi, ov, oi);
        }
        if (l == 0) { sval[w] = v; sidx[w] = bi; }
        __syncthreads();
        if (tid < 32) {
            v = sval[tid]; bi = sidx[tid];
            for (int o = 16; o; o >>= 1) {
                const float ov = __shfl_down_sync(0xffffffffu, v, o);
                const int   oi = __shfl_down_sync(0xffffffffu, bi, o);
                argmax_combine(v, bi, ov, oi);
            }
            if (tid == 0) {
                s_cur = bi;
                vis[bi >> 5] |= (1u << (bi & 31));
                g_order[b * NN + step] = bi;
            }
        }
    }
}

// ---------------- K5: gather reordered features ----------------
__global__ void kreorder(const float* __restrict__ f, float* __restrict__ out) {
    const int b = blockIdx.y, i = blockIdx.x;
    const int src = g_order[b * NN + i];
    const float4* s = (const float4*)(f + ((size_t)b * NN + src) * DD);
    float4* d = (float4*)(out + ((size_t)b * NN + i) * DD);
    d[threadIdx.x] = s[threadIdx.x];
}

__global__ void korder(float* __restrict__ out) {
    const int t = blockIdx.x * blockDim.x + threadIdx.x;
    if (t < BB * NN) out[(size_t)BB * NN * DD + t] = (float)g_order[t];
}

extern "C" void kernel_launch(void* const* d_in, const int* in_sizes, int n_in,
                              void* d_out, int out_size) {
    const float* features = (const float*)d_in[0];
    const float* coords   = (const float*)d_in[1];
    float* out = (float*)d_out;

    knorm<<<BB * NN, 256>>>(features);

    dim3 gg(NPAIR, 1, BB);
    kgemm<<<gg, 256>>>(coords);

    krowsum<<<(BB * NN + 255) / 256, 256>>>();

    kgreedy<<<BB, 1024>>>();

    dim3 rg(NN, BB);
    kreorder<<<rg, 192>>>(features, out);

    if ((long long)out_size >= (long long)BB * NN * DD + BB * NN) {
        korder<<<(BB * NN + 255) / 256, 256>>>(out);
    }
}